// round 10
// baseline (speedup 1.0000x reference)
#include <cuda_runtime.h>
#include <math.h>

#define B_    32
#define L_    64
#define D_    768
#define LL_   (L_*L_)     // 4096
#define OUTD_ (2*D_)      // 1536
#define D4_   (D_/4)      // 192
#define CH_   6           // column chunks of 128 floats
#define GRID2_ 192        // 6 * 32 blocks
#define DSMEM_ (2 * L_ * 128 * 4)   // 64 KB slice

// scratch (monotonic barrier counters -> graph-replay-safe)
__device__ float    g_pooled[B_ * D_];
__device__ float    g_tp[CH_ * B_ * 2 * L_];   // per-chunk dot partials
__device__ unsigned g_bar[4];

__device__ __forceinline__ void gsync(int i)
{
    __syncthreads();
    if (threadIdx.x == 0) {
        __threadfence();
        unsigned v = atomicAdd(&g_bar[i], 1u) + 1u;
        unsigned target = ((v - 1u) / GRID2_ + 1u) * GRID2_;
        while (*((volatile unsigned*)&g_bar[i]) < target) __nanosleep(32);
        __threadfence();
    }
    __syncthreads();
}

extern __shared__ char smem_raw[];

__global__ __launch_bounds__(256, 2) void fused(
    const float* __restrict__ a1, const float* __restrict__ a2,
    const int*   __restrict__ m1, const int*   __restrict__ m2,
    const float* __restrict__ we_w,
    const float* __restrict__ fc_w, const float* __restrict__ fc_b,
    float* __restrict__ out)
{
    // dynamic smem: phase 1-3 slice / phase B weight tile (aliased)
    float4* sa1v = (float4*)smem_raw;                 // [64*32] float4 (32 KB)
    float4* sa2v = sa1v + L_*32;                      // [64*32] float4 (32 KB)
    float4* wbv  = (float4*)smem_raw;                 // [8*192] float4 (24 KB, phase B)

    __shared__ float  t1[L_], t2[L_];
    __shared__ float  rowsh[L_], colsh[L_];
    __shared__ float  ca[L_], cb[L_];
    __shared__ float  red[8];
    __shared__ int    sl1, sl2;
    __shared__ float  smax, sinvd;
    __shared__ float4 partt[8][32];

    const int tid  = threadIdx.x;
    const int lane = tid & 31;
    const int wid  = tid >> 5;
    const int bid  = blockIdx.x;
    const int b    = bid / CH_;      // batch
    const int cc   = bid % CH_;      // column chunk (0..5)

    // ---- Phase 0: stage slice (only DRAM read of a1/a2) ----
    {
        const float4* A1 = (const float4*)(a1 + (size_t)b * L_ * D_);
        const float4* A2 = (const float4*)(a2 + (size_t)b * L_ * D_);
        #pragma unroll
        for (int k = 0; k < 8; k++) {
            int idx = tid + 256*k;        // 0..2047
            int r   = idx >> 5;
            int c   = idx & 31;
            sa1v[idx] = A1[r*D4_ + cc*32 + c];
            sa2v[idx] = A2[r*D4_ + cc*32 + c];
        }
    }
    // mask lengths meanwhile
    if (wid == 0) {
        int s = m1[b*L_ + lane] + m1[b*L_ + lane + 32];
        #pragma unroll
        for (int o = 16; o; o >>= 1) s += __shfl_xor_sync(0xffffffffu, s, o);
        if (lane == 0) sl1 = s - 2;
    } else if (wid == 1) {
        int s = m2[b*L_ + lane] + m2[b*L_ + lane + 32];
        #pragma unroll
        for (int o = 16; o; o >>= 1) s += __shfl_xor_sync(0xffffffffu, s, o);
        if (lane == 0) sl2 = s - 2;
    }
    __syncthreads();

    // ---- Phase 1: t-dot partials over this chunk ----
    {
        const float4 wv = ((const float4*)we_w)[cc*32 + lane];
        for (int t = wid; t < 2*L_; t += 8) {
            float4 v = (t < L_) ? sa1v[t*32 + lane] : sa2v[(t - L_)*32 + lane];
            float s = v.x*wv.x + v.y*wv.y + v.z*wv.z + v.w*wv.w;
            #pragma unroll
            for (int o = 16; o; o >>= 1) s += __shfl_xor_sync(0xffffffffu, s, o);
            if (lane == 0) g_tp[(cc*B_ + b)*2*L_ + t] = s;
        }
    }
    gsync(0);

    // ---- Phase 2: full t, then marginals (redundant per chunk-block) ----
    if (tid < 2*L_) {
        float s = 0.f;
        #pragma unroll
        for (int c2 = 0; c2 < CH_; c2++)
            s += g_tp[(c2*B_ + b)*2*L_ + tid];
        if (tid < L_) t1[tid] = s; else t2[tid - L_] = s;
    }
    if (tid < L_) { rowsh[tid] = 0.f; colsh[tid] = 0.f; }
    __syncthreads();

    const int l1 = sl1, l2 = sl2;

    float lmax = -1e7f;
    for (int i = wid; i < l1; i += 8) {
        const float ti = t1[i+1];
        #pragma unroll
        for (int base = 0; base < L_; base += 32) {
            int j = base + lane;
            if (j < l2) {
                float we = ti - t2[j+1];
                float m = (fabsf(we) < 1e-7f) ? -1e7f : we;
                lmax = fmaxf(lmax, m);
            }
        }
    }
    #pragma unroll
    for (int o = 16; o; o >>= 1) lmax = fmaxf(lmax, __shfl_xor_sync(0xffffffffu, lmax, o));
    if (lane == 0) red[wid] = lmax;
    __syncthreads();
    if (tid == 0) {
        float m = red[0];
        #pragma unroll
        for (int i = 1; i < 8; i++) m = fmaxf(m, red[i]);
        smax = m;
    }
    __syncthreads();
    const float mx = smax;

    for (int i = wid; i < l1; i += 8) {
        const float ti = t1[i+1];
        float s = 0.f;
        #pragma unroll
        for (int base = 0; base < L_; base += 32) {
            int j = base + lane;
            if (j < l2) {
                float we = ti - t2[j+1];
                float m = (fabsf(we) < 1e-7f) ? -1e7f : we;
                s += __expf(m - mx);
            }
        }
        #pragma unroll
        for (int o = 16; o; o >>= 1) s += __shfl_xor_sync(0xffffffffu, s, o);
        if (lane == 0) rowsh[i] = s;
    }
    for (int j = wid; j < l2; j += 8) {
        const float tj = t2[j+1];
        float s = 0.f;
        #pragma unroll
        for (int base = 0; base < L_; base += 32) {
            int i = base + lane;
            if (i < l1) {
                float we = t1[i+1] - tj;
                float m = (fabsf(we) < 1e-7f) ? -1e7f : we;
                s += __expf(m - mx);
            }
        }
        #pragma unroll
        for (int o = 16; o; o >>= 1) s += __shfl_xor_sync(0xffffffffu, s, o);
        if (lane == 0) colsh[j] = s;
    }
    __syncthreads();

    if (wid == 0) {
        float s = rowsh[lane] + rowsh[lane + 32];
        #pragma unroll
        for (int o = 16; o; o >>= 1) s += __shfl_xor_sync(0xffffffffu, s, o);
        if (lane == 0) {
            float pad = (float)(LL_ - l1*l2) * __expf(-1e7f - mx);
            sinvd = 1.f / (s + pad);
        }
    }
    __syncthreads();
    const float invd = sinvd;

    if (tid < L_) {
        ca[tid] = (tid >= 1 && tid - 1 < l1) ? rowsh[tid-1] * invd : 0.f;
    } else if (tid < 2*L_) {
        int j = tid - L_;
        cb[j] = (j >= 1 && j - 1 < l2) ? -colsh[j-1] * invd : 0.f;
    }
    __syncthreads();

    // ---- Phase 3: pooled chunk directly from resident smem slice ----
    {
        float4 acc = make_float4(0.f, 0.f, 0.f, 0.f);
        #pragma unroll
        for (int k = 0; k < 8; k++) {
            const int r = wid + 8*k;
            const float c1 = ca[r];
            const float c2 = cb[r];
            float4 v1 = sa1v[r*32 + lane];
            float4 v2 = sa2v[r*32 + lane];
            acc.x += c1*v1.x + c2*v2.x;
            acc.y += c1*v1.y + c2*v2.y;
            acc.z += c1*v1.z + c2*v2.z;
            acc.w += c1*v1.w + c2*v2.w;
        }
        partt[wid][lane] = acc;
        __syncthreads();
        if (tid < 32) {
            float4 s = partt[0][lane];
            #pragma unroll
            for (int k = 1; k < 8; k++) {
                float4 v = partt[k][lane];
                s.x += v.x; s.y += v.y; s.z += v.z; s.w += v.w;
            }
            ((float4*)g_pooled)[b*D4_ + cc*32 + lane] = s;
        }
    }
    gsync(1);

    // ---- Phase B: one 8-row fc_w tile per block ----
    {
        const int o0 = bid * 8;
        const float4* fw4 = (const float4*)fc_w;
        #pragma unroll
        for (int k = 0; k < 6; k++)
            wbv[tid + 256*k] = fw4[(size_t)o0*D4_ + tid + 256*k];
        __syncthreads();

        const float4* poolv = (const float4*)g_pooled;
        #pragma unroll
        for (int g = 0; g < 2; g++) {
            const int b0 = wid*2 + g*16;
            float4 p[2][6];
            #pragma unroll
            for (int bb = 0; bb < 2; bb++)
                #pragma unroll
                for (int k = 0; k < 6; k++)
                    p[bb][k] = poolv[(b0 + bb)*D4_ + lane + 32*k];

            #pragma unroll
            for (int r = 0; r < 8; r++) {
                const int o = o0 + r;
                float x0 = 0.f, x1 = 0.f;
                #pragma unroll
                for (int k = 0; k < 6; k++) {
                    float4 w = wbv[r*D4_ + lane + 32*k];
                    x0 += w.x*p[0][k].x + w.y*p[0][k].y + w.z*p[0][k].z + w.w*p[0][k].w;
                    x1 += w.x*p[1][k].x + w.y*p[1][k].y + w.z*p[1][k].z + w.w*p[1][k].w;
                }
                #pragma unroll
                for (int off = 16; off; off >>= 1) {
                    x0 += __shfl_xor_sync(0xffffffffu, x0, off);
                    x1 += __shfl_xor_sync(0xffffffffu, x1, off);
                }
                if (lane == 0) {
                    const float bias = fc_b[o];
                    out[(size_t)(b0+0)*OUTD_ + o] = tanhf(x0 + bias);
                    out[(size_t)(b0+1)*OUTD_ + o] = tanhf(x1 + bias);
                }
            }
        }
    }
}

extern "C" void kernel_launch(void* const* d_in, const int* in_sizes, int n_in,
                              void* d_out, int out_size)
{
    const float* a1   = (const float*)d_in[0];  // (B, L, D)
    const float* a2   = (const float*)d_in[1];  // (B, L, D)
    const int*   m1   = (const int*)  d_in[2];  // (B, L)
    const int*   m2   = (const int*)  d_in[3];  // (B, L)
    const float* we_w = (const float*)d_in[4];  // (1, D)
    const float* fc_w = (const float*)d_in[5];  // (2D, D)
    const float* fc_b = (const float*)d_in[6];  // (2D,)
    float* out = (float*)d_out;                 // (B, 2D)

    static int attr_set = 0;
    if (!attr_set) {
        cudaFuncSetAttribute(fused, cudaFuncAttributeMaxDynamicSharedMemorySize, DSMEM_);
        attr_set = 1;
    }
    fused<<<GRID2_, 256, DSMEM_>>>(a1, a2, m1, m2, we_w, fc_w, fc_b, out);
}

// round 11
// speedup vs baseline: 1.2527x; 1.2527x over previous
#include <cuda_runtime.h>
#include <math.h>

#define B_    32
#define L_    64
#define D_    768
#define LL_   (L_*L_)     // 4096
#define OUTD_ (2*D_)      // 1536
#define D4_   (D_/4)      // 192

// scratch
__device__ float g_pooled[B_ * D_];
__device__ float g_t[B_ * 2 * L_];   // t1 (64) then t2 (64) per batch

// ---------------------------------------------------------------------------
// T: t[b, r] = dot(row, we_w). grid = 128 x 1024 (32 warps). Exactly one warp
// per (batch,row) task; single wave; minimal issue.
// ---------------------------------------------------------------------------
__global__ __launch_bounds__(1024) void stageT(
    const float* __restrict__ a1, const float* __restrict__ a2,
    const float* __restrict__ we_w)
{
    __shared__ float sw[D_];
    const int tid  = threadIdx.x;
    const int lane = tid & 31;
    const int wid  = tid >> 5;
    const int w    = blockIdx.x * 32 + wid;   // 0..4095

    for (int i = tid; i < D_; i += 1024) sw[i] = we_w[i];
    __syncthreads();

    const int b = w >> 7;
    const int r = w & 127;
    const float4* row = (r < L_)
        ? ((const float4*)(a1 + (size_t)b * L_ * D_) + r * D4_)
        : ((const float4*)(a2 + (size_t)b * L_ * D_) + (r - L_) * D4_);
    const float4* swv = (const float4*)sw;

    float s = 0.f;
    #pragma unroll
    for (int k = 0; k < 6; k++) {
        float4 v = row[lane + 32*k];
        float4 wv = swv[lane + 32*k];
        s += v.x*wv.x + v.y*wv.y + v.z*wv.z + v.w*wv.w;
    }
    #pragma unroll
    for (int o = 16; o; o >>= 1) s += __shfl_xor_sync(0xffffffffu, s, o);
    if (lane == 0) g_t[b * 2*L_ + r] = s;
}

// ---------------------------------------------------------------------------
// MA2: marginals (no max-subtract: logits are O(10), exp is fp32-safe; softmax
// is shift-invariant so the result is identical) + pooled chunk.
// grid = (6, B_) = 192 blocks, 256 threads.
// ---------------------------------------------------------------------------
__global__ __launch_bounds__(256) void stageMA2(
    const float* __restrict__ a1, const float* __restrict__ a2,
    const int*   __restrict__ m1, const int*   __restrict__ m2)
{
    __shared__ float  t1[L_], t2[L_];
    __shared__ float  rowsh[L_], colsh[L_];
    __shared__ float  ca[L_], cb[L_];
    __shared__ int    sl1, sl2;
    __shared__ float  sinvd;
    __shared__ float4 partt[8][32];

    const int b    = blockIdx.y;
    const int cc   = blockIdx.x;
    const int tid  = threadIdx.x;
    const int lane = tid & 31;
    const int wid  = tid >> 5;

    if (tid < 2*L_) {
        float v = g_t[b*2*L_ + tid];
        if (tid < L_) t1[tid] = v; else t2[tid - L_] = v;
    }
    if (tid < L_) { rowsh[tid] = 0.f; colsh[tid] = 0.f; }

    if (wid == 0) {
        int s = m1[b*L_ + lane] + m1[b*L_ + lane + 32];
        #pragma unroll
        for (int o = 16; o; o >>= 1) s += __shfl_xor_sync(0xffffffffu, s, o);
        if (lane == 0) sl1 = s - 2;
    } else if (wid == 1) {
        int s = m2[b*L_ + lane] + m2[b*L_ + lane + 32];
        #pragma unroll
        for (int o = 16; o; o >>= 1) s += __shfl_xor_sync(0xffffffffu, s, o);
        if (lane == 0) sl2 = s - 2;
    }
    __syncthreads();

    const int l1 = sl1, l2 = sl2;

    // row sums: rowsh[i] = sum_j exp(masked(t1[i+1]-t2[j+1]))
    for (int i = wid; i < l1; i += 8) {
        const float ti = t1[i+1];
        float s = 0.f;
        #pragma unroll
        for (int base = 0; base < L_; base += 32) {
            int j = base + lane;
            if (j < l2) {
                float we = ti - t2[j+1];
                float m = (fabsf(we) < 1e-7f) ? -1e7f : we;
                s += __expf(m);
            }
        }
        #pragma unroll
        for (int o = 16; o; o >>= 1) s += __shfl_xor_sync(0xffffffffu, s, o);
        if (lane == 0) rowsh[i] = s;
    }
    // col sums
    for (int j = wid; j < l2; j += 8) {
        const float tj = t2[j+1];
        float s = 0.f;
        #pragma unroll
        for (int base = 0; base < L_; base += 32) {
            int i = base + lane;
            if (i < l1) {
                float we = t1[i+1] - tj;
                float m = (fabsf(we) < 1e-7f) ? -1e7f : we;
                s += __expf(m);
            }
        }
        #pragma unroll
        for (int o = 16; o; o >>= 1) s += __shfl_xor_sync(0xffffffffu, s, o);
        if (lane == 0) colsh[j] = s;
    }
    __syncthreads();

    // denom = sum(rowsums); padding terms exp(-1e7) underflow to 0
    if (wid == 0) {
        float s = rowsh[lane] + rowsh[lane + 32];
        #pragma unroll
        for (int o = 16; o; o >>= 1) s += __shfl_xor_sync(0xffffffffu, s, o);
        if (lane == 0) sinvd = 1.f / s;
    }
    __syncthreads();
    const float invd = sinvd;

    if (tid < L_) {
        ca[tid] = (tid >= 1 && tid - 1 < l1) ? rowsh[tid-1] * invd : 0.f;
    } else if (tid < 2*L_) {
        int j = tid - L_;
        cb[j] = (j >= 1 && j - 1 < l2) ? -colsh[j-1] * invd : 0.f;
    }
    __syncthreads();

    // pooled chunk: columns [cc*32, cc*32+32)
    const int col = cc*32 + lane;
    const float4* base1v = (const float4*)(a1 + (size_t)b * L_ * D_);
    const float4* base2v = (const float4*)(a2 + (size_t)b * L_ * D_);

    float4 acc = make_float4(0.f, 0.f, 0.f, 0.f);
    #pragma unroll
    for (int k = 0; k < 8; k++) {
        const int r = wid + 8*k;
        const float c1 = ca[r];
        const float c2 = cb[r];
        float4 v1 = base1v[r*D4_ + col];
        float4 v2 = base2v[r*D4_ + col];
        acc.x += c1*v1.x + c2*v2.x;
        acc.y += c1*v1.y + c2*v2.y;
        acc.z += c1*v1.z + c2*v2.z;
        acc.w += c1*v1.w + c2*v2.w;
    }
    partt[wid][lane] = acc;
    __syncthreads();

    if (tid < 32) {
        float4 s = partt[0][lane];
        #pragma unroll
        for (int k = 1; k < 8; k++) {
            float4 v = partt[k][lane];
            s.x += v.x; s.y += v.y; s.z += v.z; s.w += v.w;
        }
        ((float4*)g_pooled)[b*D4_ + col] = s;
    }
}

// ---------------------------------------------------------------------------
// B: out[b,o] = tanh( dot(pooled[b], fc_w[o]) + fc_b[o] )
// grid = 192, block = 512 (16 warps). One 8-row tile per block.
// ---------------------------------------------------------------------------
__global__ __launch_bounds__(512) void stageB(
    const float* __restrict__ fc_w, const float* __restrict__ fc_b,
    float* __restrict__ out)
{
    __shared__ float sB[8 * D_];   // 24 KB

    const int tid  = threadIdx.x;
    const int lane = tid & 31;
    const int wid  = tid >> 5;
    const int o0   = blockIdx.x * 8;
    const int b0   = wid * 2;

    {
        const float4* src = (const float4*)(fc_w + (size_t)o0 * D_);
        float4*       dst = (float4*)sB;
        #pragma unroll
        for (int k = 0; k < 3; k++)
            dst[tid + 512*k] = src[tid + 512*k];
    }

    const float4* poolv = (const float4*)g_pooled;
    float4 p[2][6];
    #pragma unroll
    for (int bb = 0; bb < 2; bb++)
        #pragma unroll
        for (int k = 0; k < 6; k++)
            p[bb][k] = poolv[(b0 + bb)*D4_ + lane + 32*k];

    __syncthreads();

    const float4* sBv = (const float4*)sB;
    #pragma unroll
    for (int r = 0; r < 8; r++) {
        const int o = o0 + r;
        float x0 = 0.f, x1 = 0.f;
        #pragma unroll
        for (int k = 0; k < 6; k++) {
            float4 w = sBv[r*D4_ + lane + 32*k];
            x0 += w.x*p[0][k].x + w.y*p[0][k].y + w.z*p[0][k].z + w.w*p[0][k].w;
            x1 += w.x*p[1][k].x + w.y*p[1][k].y + w.z*p[1][k].z + w.w*p[1][k].w;
        }
        #pragma unroll
        for (int off = 16; off; off >>= 1) {
            x0 += __shfl_xor_sync(0xffffffffu, x0, off);
            x1 += __shfl_xor_sync(0xffffffffu, x1, off);
        }
        if (lane == 0) {
            const float bias = fc_b[o];
            out[(size_t)(b0+0)*OUTD_ + o] = tanhf(x0 + bias);
            out[(size_t)(b0+1)*OUTD_ + o] = tanhf(x1 + bias);
        }
    }
}

extern "C" void kernel_launch(void* const* d_in, const int* in_sizes, int n_in,
                              void* d_out, int out_size)
{
    const float* a1   = (const float*)d_in[0];  // (B, L, D)
    const float* a2   = (const float*)d_in[1];  // (B, L, D)
    const int*   m1   = (const int*)  d_in[2];  // (B, L)
    const int*   m2   = (const int*)  d_in[3];  // (B, L)
    const float* we_w = (const float*)d_in[4];  // (1, D)
    const float* fc_w = (const float*)d_in[5];  // (2D, D)
    const float* fc_b = (const float*)d_in[6];  // (2D,)
    float* out = (float*)d_out;                 // (B, 2D)

    stageT<<<128, 1024>>>(a1, a2, we_w);
    stageMA2<<<dim3(6, B_), 256>>>(a1, a2, m1, m2);
    stageB<<<OUTD_/8, 512>>>(fc_w, fc_b, out);
}

// round 12
// speedup vs baseline: 1.3924x; 1.1115x over previous
#include <cuda_runtime.h>
#include <math.h>

#define B_    32
#define L_    64
#define D_    768
#define LL_   (L_*L_)     // 4096
#define OUTD_ (2*D_)      // 1536
#define D4_   (D_/4)      // 192

// scratch
__device__ float g_pooled[B_ * D_];

// ---------------------------------------------------------------------------
// K1: per-batch fused t-dots -> masked softmax marginals -> pooled.
// grid = 32 (one block per batch), block = 1024 (32 warps).
// t values live only in shared memory (no global round-trip).
// ---------------------------------------------------------------------------
__global__ __launch_bounds__(1024) void stageTMA(
    const float* __restrict__ a1, const float* __restrict__ a2,
    const int*   __restrict__ m1, const int*   __restrict__ m2,
    const float* __restrict__ we_w)
{
    __shared__ float  sw[D_];               // 3 KB
    __shared__ float  t1[L_], t2[L_];
    __shared__ float  rowsh[L_], colsh[L_];
    __shared__ float  ca[L_], cb[L_];
    __shared__ float  sinvd;
    __shared__ int    sl1, sl2;
    __shared__ float4 pp[4][D4_];           // 12 KB pooled partials

    const int b    = blockIdx.x;
    const int tid  = threadIdx.x;
    const int lane = tid & 31;
    const int wid  = tid >> 5;              // 0..31

    // we_w to smem + mask lengths
    if (tid < D_) sw[tid] = we_w[tid];
    if (tid < L_) { rowsh[tid] = 0.f; colsh[tid] = 0.f; }
    if (wid == 0) {
        int s = m1[b*L_ + lane] + m1[b*L_ + lane + 32];
        #pragma unroll
        for (int o = 16; o; o >>= 1) s += __shfl_xor_sync(0xffffffffu, s, o);
        if (lane == 0) sl1 = s - 2;
    } else if (wid == 1) {
        int s = m2[b*L_ + lane] + m2[b*L_ + lane + 32];
        #pragma unroll
        for (int o = 16; o; o >>= 1) s += __shfl_xor_sync(0xffffffffu, s, o);
        if (lane == 0) sl2 = s - 2;
    }
    __syncthreads();

    const float4* base1v = (const float4*)(a1 + (size_t)b * L_ * D_);
    const float4* base2v = (const float4*)(a2 + (size_t)b * L_ * D_);
    const float4* swv    = (const float4*)sw;

    // ---- Phase t: 128 row tasks over 32 warps (4 each, 2x2 pipelined) ----
    #pragma unroll
    for (int rr = 0; rr < 4; rr += 2) {
        const int taskA = wid + 32*rr;
        const int taskB = wid + 32*(rr+1);
        const float4* rowA = (taskA < L_) ? (base1v + taskA*D4_) : (base2v + (taskA-L_)*D4_);
        const float4* rowB = (taskB < L_) ? (base1v + taskB*D4_) : (base2v + (taskB-L_)*D4_);
        float4 va[6], vb[6];
        #pragma unroll
        for (int k = 0; k < 6; k++) va[k] = rowA[lane + 32*k];
        #pragma unroll
        for (int k = 0; k < 6; k++) vb[k] = rowB[lane + 32*k];
        float sA = 0.f, sB = 0.f;
        #pragma unroll
        for (int k = 0; k < 6; k++) {
            float4 wv = swv[lane + 32*k];
            sA += va[k].x*wv.x + va[k].y*wv.y + va[k].z*wv.z + va[k].w*wv.w;
            sB += vb[k].x*wv.x + vb[k].y*wv.y + vb[k].z*wv.z + vb[k].w*wv.w;
        }
        #pragma unroll
        for (int o = 16; o; o >>= 1) {
            sA += __shfl_xor_sync(0xffffffffu, sA, o);
            sB += __shfl_xor_sync(0xffffffffu, sB, o);
        }
        if (lane == 0) {
            if (taskA < L_) t1[taskA] = sA; else t2[taskA - L_] = sA;
            if (taskB < L_) t1[taskB] = sB; else t2[taskB - L_] = sB;
        }
    }
    __syncthreads();

    const int l1 = sl1, l2 = sl2;

    // ---- Marginals (no max-subtract: logits O(10), softmax shift-invariant;
    //      padding exp(-1e7) underflows to 0) ----
    for (int i = wid; i < l1; i += 32) {
        const float ti = t1[i+1];
        float s = 0.f;
        #pragma unroll
        for (int base = 0; base < L_; base += 32) {
            int j = base + lane;
            if (j < l2) {
                float we = ti - t2[j+1];
                float m = (fabsf(we) < 1e-7f) ? -1e7f : we;
                s += __expf(m);
            }
        }
        #pragma unroll
        for (int o = 16; o; o >>= 1) s += __shfl_xor_sync(0xffffffffu, s, o);
        if (lane == 0) rowsh[i] = s;
    }
    for (int j = wid; j < l2; j += 32) {
        const float tj = t2[j+1];
        float s = 0.f;
        #pragma unroll
        for (int base = 0; base < L_; base += 32) {
            int i = base + lane;
            if (i < l1) {
                float we = t1[i+1] - tj;
                float m = (fabsf(we) < 1e-7f) ? -1e7f : we;
                s += __expf(m);
            }
        }
        #pragma unroll
        for (int o = 16; o; o >>= 1) s += __shfl_xor_sync(0xffffffffu, s, o);
        if (lane == 0) colsh[j] = s;
    }
    __syncthreads();

    if (wid == 0) {
        float s = rowsh[lane] + rowsh[lane + 32];
        #pragma unroll
        for (int o = 16; o; o >>= 1) s += __shfl_xor_sync(0xffffffffu, s, o);
        if (lane == 0) sinvd = 1.f / s;
    }
    __syncthreads();
    const float invd = sinvd;

    if (tid < L_) {
        ca[tid] = (tid >= 1 && tid - 1 < l1) ? rowsh[tid-1] * invd : 0.f;
    } else if (tid < 2*L_) {
        int j = tid - L_;
        cb[j] = (j >= 1 && j - 1 < l2) ? -colsh[j-1] * invd : 0.f;
    }
    __syncthreads();

    // ---- Pooled: 768 active threads; c4 = tid%192, row-group = tid/192 ----
    if (tid < 4*D4_) {
        const int c4 = tid % D4_;
        const int rg = tid / D4_;          // 0..3, rows rg*16 .. rg*16+15
        float4 acc = make_float4(0.f, 0.f, 0.f, 0.f);
        #pragma unroll
        for (int k = 0; k < 16; k++) {
            const int r = rg*16 + k;
            const float c1 = ca[r];
            const float c2 = cb[r];
            float4 v1 = base1v[r*D4_ + c4];
            float4 v2 = base2v[r*D4_ + c4];
            acc.x += c1*v1.x + c2*v2.x;
            acc.y += c1*v1.y + c2*v2.y;
            acc.z += c1*v1.z + c2*v2.z;
            acc.w += c1*v1.w + c2*v2.w;
        }
        pp[rg][c4] = acc;
    }
    __syncthreads();

    if (tid < D4_) {
        float4 s = pp[0][tid];
        #pragma unroll
        for (int k = 1; k < 4; k++) {
            float4 v = pp[k][tid];
            s.x += v.x; s.y += v.y; s.z += v.z; s.w += v.w;
        }
        ((float4*)g_pooled)[b*D4_ + tid] = s;
    }
}

// ---------------------------------------------------------------------------
// K2: out[b,o] = tanh( dot(pooled[b], fc_w[o]) + fc_b[o] )
// grid = 192, block = 512 (16 warps). One 8-row tile per block.
// ---------------------------------------------------------------------------
__global__ __launch_bounds__(512) void stageB(
    const float* __restrict__ fc_w, const float* __restrict__ fc_b,
    float* __restrict__ out)
{
    __shared__ float sB[8 * D_];   // 24 KB

    const int tid  = threadIdx.x;
    const int lane = tid & 31;
    const int wid  = tid >> 5;
    const int o0   = blockIdx.x * 8;
    const int b0   = wid * 2;

    {
        const float4* src = (const float4*)(fc_w + (size_t)o0 * D_);
        float4*       dst = (float4*)sB;
        #pragma unroll
        for (int k = 0; k < 3; k++)
            dst[tid + 512*k] = src[tid + 512*k];
    }

    const float4* poolv = (const float4*)g_pooled;
    float4 p[2][6];
    #pragma unroll
    for (int bb = 0; bb < 2; bb++)
        #pragma unroll
        for (int k = 0; k < 6; k++)
            p[bb][k] = poolv[(b0 + bb)*D4_ + lane + 32*k];

    __syncthreads();

    const float4* sBv = (const float4*)sB;
    #pragma unroll
    for (int r = 0; r < 8; r++) {
        const int o = o0 + r;
        float x0 = 0.f, x1 = 0.f;
        #pragma unroll
        for (int k = 0; k < 6; k++) {
            float4 w = sBv[r*D4_ + lane + 32*k];
            x0 += w.x*p[0][k].x + w.y*p[0][k].y + w.z*p[0][k].z + w.w*p[0][k].w;
            x1 += w.x*p[1][k].x + w.y*p[1][k].y + w.z*p[1][k].z + w.w*p[1][k].w;
        }
        #pragma unroll
        for (int off = 16; off; off >>= 1) {
            x0 += __shfl_xor_sync(0xffffffffu, x0, off);
            x1 += __shfl_xor_sync(0xffffffffu, x1, off);
        }
        if (lane == 0) {
            const float bias = fc_b[o];
            out[(size_t)(b0+0)*OUTD_ + o] = tanhf(x0 + bias);
            out[(size_t)(b0+1)*OUTD_ + o] = tanhf(x1 + bias);
        }
    }
}

extern "C" void kernel_launch(void* const* d_in, const int* in_sizes, int n_in,
                              void* d_out, int out_size)
{
    const float* a1   = (const float*)d_in[0];  // (B, L, D)
    const float* a2   = (const float*)d_in[1];  // (B, L, D)
    const int*   m1   = (const int*)  d_in[2];  // (B, L)
    const int*   m2   = (const int*)  d_in[3];  // (B, L)
    const float* we_w = (const float*)d_in[4];  // (1, D)
    const float* fc_w = (const float*)d_in[5];  // (2D, D)
    const float* fc_b = (const float*)d_in[6];  // (2D,)
    float* out = (float*)d_out;                 // (B, 2D)

    stageTMA<<<B_, 1024>>>(a1, a2, m1, m2, we_w);
    stageB<<<OUTD_/8, 512>>>(fc_w, fc_b, out);
}